// round 4
// baseline (speedup 1.0000x reference)
#include <cuda_runtime.h>
#include <cuda_bf16.h>
#include <cstdint>

// Shape fixed by dataset: B=4, Q=V=4096, H=128, out = attention with
// scale = sqrt(128) (multiply!) and deterministic JAX dropout p=0.1, key 42.
#define Bn 4
#define Qn 4096
#define Vv 4096
#define Hn 128
#define TQ 64
#define TV 64
#define NT 256
#define LDQ 132   // padded row stride for Q/K/V tiles (floats)
#define LDS 80    // padded row stride for P tile (floats)

static constexpr float SCALE_F = 11.313708498984761f;  // sqrt(128)

// smem layout (floats)
#define OFF_Q 0
#define OFF_K (64 * LDQ)            // 8448 — shared K/V buffer
#define OFF_S (2 * 64 * LDQ)        // 16896
#define SMEMF (2 * 64 * LDQ + 64 * LDS)
#define SMEM_BYTES (SMEMF * 4)      // 88064 B

__device__ __forceinline__ uint32_t rotl32(uint32_t x, int d) {
    return __funnelshift_l(x, x, d);
}

// JAX threefry2x32, key=(0,42), counter=(hi=0, lo=j)  [partitionable variant:
// 32-bit draw = out0 ^ out1].
__device__ __forceinline__ uint32_t threefry_bits(uint32_t j) {
    const uint32_t K0 = 0u, K1 = 42u;
    const uint32_t K2 = 0x1BD11BDAu ^ K0 ^ K1;
    uint32_t x0 = K0;        // ctr_hi + ks0
    uint32_t x1 = j + K1;    // ctr_lo + ks1
#define R1(r) { x0 += x1; x1 = rotl32(x1, (r)); x1 ^= x0; }
    R1(13) R1(15) R1(26) R1(6)   x0 += K1; x1 += K2 + 1u;
    R1(17) R1(29) R1(16) R1(24)  x0 += K2; x1 += K0 + 2u;
    R1(13) R1(15) R1(26) R1(6)   x0 += K0; x1 += K1 + 3u;
    R1(17) R1(29) R1(16) R1(24)  x0 += K1; x1 += K2 + 4u;
    R1(13) R1(15) R1(26) R1(6)   x0 += K2; x1 += K0 + 5u;
#undef R1
    return x0 ^ x1;
}

__device__ __forceinline__ bool keepf(uint32_t j) {
    uint32_t bits = threefry_bits(j);
    float u = __uint_as_float((bits >> 9) | 0x3f800000u) - 1.0f;
    return u < 0.9f;
}

__global__ __launch_bounds__(NT, 2)
void attn_kernel(const float* __restrict__ Qg, const float* __restrict__ Kg,
                 const float* __restrict__ Vg, float* __restrict__ Og)
{
    extern __shared__ float sm[];
    float* Qs = sm + OFF_Q;
    float* KV = sm + OFF_K;
    float* Sb = sm + OFF_S;

    const int tid = threadIdx.x;
    const int tx = tid & 15;   // 0..15
    const int ty = tid >> 4;   // 0..15
    const int b  = blockIdx.y;
    const int q0 = blockIdx.x * TQ;

    // ---- load Q tile [64][128] into Qs (stride LDQ), coalesced ----
    {
        const float* qp = Qg + ((size_t)(b * Qn + q0)) * Hn;
        #pragma unroll
        for (int e = 0; e < 8; e++) {
            int idx = tid + NT * e;
            int r = idx >> 5, c = (idx & 31) << 2;
            *(float4*)&Qs[r * LDQ + c] = *(const float4*)&qp[r * Hn + c];
        }
    }

    float m[4], z[4];
    #pragma unroll
    for (int i = 0; i < 4; i++) { m[i] = -INFINITY; z[i] = 0.0f; }
    float O[4][8];
    #pragma unroll
    for (int i = 0; i < 4; i++)
        #pragma unroll
        for (int c = 0; c < 8; c++) O[i][c] = 0.0f;

    for (int vt = 0; vt < Vv; vt += TV) {
        __syncthreads();  // previous PV done with KV & Sb

        // ---- load K tile [64][128] into KV ----
        {
            const float* kp = Kg + ((size_t)(b * Vv + vt)) * Hn;
            #pragma unroll
            for (int e = 0; e < 8; e++) {
                int idx = tid + NT * e;
                int r = idx >> 5, c = (idx & 31) << 2;
                *(float4*)&KV[r * LDQ + c] = *(const float4*)&kp[r * Hn + c];
            }
        }
        __syncthreads();

        // ---- S = Q K^T : 4x4 microtile (rows ty+16i, cols tx+16j) ----
        float acc[4][4];
        #pragma unroll
        for (int i = 0; i < 4; i++)
            #pragma unroll
            for (int j = 0; j < 4; j++) acc[i][j] = 0.0f;

        #pragma unroll 2
        for (int kk = 0; kk < Hn; kk += 4) {
            float4 qv[4], kv[4];
            #pragma unroll
            for (int i = 0; i < 4; i++)
                qv[i] = *(const float4*)&Qs[(ty + 16 * i) * LDQ + kk];
            #pragma unroll
            for (int j = 0; j < 4; j++)
                kv[j] = *(const float4*)&KV[(tx + 16 * j) * LDQ + kk];
            #pragma unroll
            for (int i = 0; i < 4; i++)
                #pragma unroll
                for (int j = 0; j < 4; j++) {
                    acc[i][j] += qv[i].x * kv[j].x;
                    acc[i][j] += qv[i].y * kv[j].y;
                    acc[i][j] += qv[i].z * kv[j].z;
                    acc[i][j] += qv[i].w * kv[j].w;
                }
        }
        __syncthreads();  // all threads done reading K before V overwrites

        // ---- load V tile into KV (reuse buffer) ----
        {
            const float* vp = Vg + ((size_t)(b * Vv + vt)) * Hn;
            #pragma unroll
            for (int e = 0; e < 8; e++) {
                int idx = tid + NT * e;
                int r = idx >> 5, c = (idx & 31) << 2;
                *(float4*)&KV[r * LDQ + c] = *(const float4*)&vp[r * Hn + c];
            }
        }

        // ---- online softmax + dropout; write masked P into Sb ----
        #pragma unroll
        for (int i = 0; i < 4; i++) {
            float s0 = acc[i][0] * SCALE_F, s1 = acc[i][1] * SCALE_F;
            float s2 = acc[i][2] * SCALE_F, s3 = acc[i][3] * SCALE_F;
            float t = fmaxf(fmaxf(s0, s1), fmaxf(s2, s3));
            #pragma unroll
            for (int o = 1; o < 16; o <<= 1)
                t = fmaxf(t, __shfl_xor_sync(0xffffffffu, t, o, 16));
            float nm = fmaxf(m[i], t);
            float al = __expf(m[i] - nm);
            float p0 = __expf(s0 - nm), p1 = __expf(s1 - nm);
            float p2 = __expf(s2 - nm), p3 = __expf(s3 - nm);
            float zs = p0 + p1 + p2 + p3;
            #pragma unroll
            for (int o = 1; o < 16; o <<= 1)
                zs += __shfl_xor_sync(0xffffffffu, zs, o, 16);
            z[i] = z[i] * al + zs;
            m[i] = nm;
            #pragma unroll
            for (int c = 0; c < 8; c++) O[i][c] *= al;

            uint32_t base = (uint32_t)(b * Qn + q0 + ty + 16 * i) * (uint32_t)Vv
                          + (uint32_t)(vt + tx);
            float* srow = &Sb[(ty + 16 * i) * LDS + tx];
            srow[0]  = keepf(base)       ? p0 : 0.0f;
            srow[16] = keepf(base + 16u) ? p1 : 0.0f;
            srow[32] = keepf(base + 32u) ? p2 : 0.0f;
            srow[48] = keepf(base + 48u) ? p3 : 0.0f;
        }
        __syncthreads();  // V tile + Sb ready

        // ---- O += P @ V : rows ty+16i, cols 4tx..4tx+3 and 64+4tx.. ----
        #pragma unroll 4
        for (int v = 0; v < TV; v++) {
            float4 va = *(const float4*)&KV[v * LDQ + 4 * tx];
            float4 vb = *(const float4*)&KV[v * LDQ + 64 + 4 * tx];
            #pragma unroll
            for (int i = 0; i < 4; i++) {
                float p = Sb[(ty + 16 * i) * LDS + v];
                O[i][0] += p * va.x; O[i][1] += p * va.y;
                O[i][2] += p * va.z; O[i][3] += p * va.w;
                O[i][4] += p * vb.x; O[i][5] += p * vb.y;
                O[i][6] += p * vb.z; O[i][7] += p * vb.w;
            }
        }
    }

    // ---- epilogue: out = O / (0.9 * Z) ----
    float* op = Og + ((size_t)(b * Qn + q0)) * Hn;
    #pragma unroll
    for (int i = 0; i < 4; i++) {
        int r = ty + 16 * i;
        float invz = 1.0f / (0.9f * z[i]);
        float4 o1 = make_float4(O[i][0] * invz, O[i][1] * invz,
                                O[i][2] * invz, O[i][3] * invz);
        float4 o2 = make_float4(O[i][4] * invz, O[i][5] * invz,
                                O[i][6] * invz, O[i][7] * invz);
        *(float4*)&op[r * Hn + 4 * tx] = o1;
        *(float4*)&op[r * Hn + 64 + 4 * tx] = o2;
    }
}

extern "C" void kernel_launch(void* const* d_in, const int* in_sizes, int n_in,
                              void* d_out, int out_size) {
    const float* Qg = (const float*)d_in[0];
    const float* Kg = (const float*)d_in[1];
    const float* Vg = (const float*)d_in[2];
    float* Og = (float*)d_out;
    (void)in_sizes; (void)n_in; (void)out_size;

    cudaFuncSetAttribute(attn_kernel,
                         cudaFuncAttributeMaxDynamicSharedMemorySize, SMEM_BYTES);
    dim3 grid(Qn / TQ, Bn);
    attn_kernel<<<grid, NT, SMEM_BYTES>>>(Qg, Kg, Vg, Og);
}

// round 5
// speedup vs baseline: 1.6904x; 1.6904x over previous
#include <cuda_runtime.h>
#include <cuda_bf16.h>
#include <cstdint>

// B=4, Q=V=4096, H=128; out = softmax(sqrt(128)*QK^T) with deterministic
// JAX dropout (p=0.1, key 42), then @V.
#define Bn 4
#define Qn 4096
#define Vv 4096
#define Hn 128
#define TQ 64
#define TV 64
#define NT 256
#define LDQ 132   // padded row stride for Q/K tiles (floats)
#define LDS 80    // padded row stride for P tile (floats)

static constexpr float SCALE_F = 11.313708498984761f;  // sqrt(128)
static constexpr float CUT = 1e-8f;  // negligible-probability cutoff

// smem layout (floats)
#define OFF_Q 0
#define OFF_K (64 * LDQ)                  // 8448
#define OFF_S (2 * 64 * LDQ)              // 16896
#define OFF_C (2 * 64 * LDQ + 64 * LDS)   // colhot (2 words)
#define SMEMF (OFF_C + 4)
#define SMEM_BYTES (SMEMF * 4)

__device__ __forceinline__ uint32_t rotl32(uint32_t x, int d) {
    return __funnelshift_l(x, x, d);
}

// JAX threefry2x32, key=(0,42), counter=(hi=0, lo=j); draw = x0 ^ x1.
// (Validated: rel_err 4.8e-8 in round 3.)
__device__ __forceinline__ uint32_t threefry_bits(uint32_t j) {
    const uint32_t K0 = 0u, K1 = 42u;
    const uint32_t K2 = 0x1BD11BDAu ^ K0 ^ K1;
    uint32_t x0 = K0;
    uint32_t x1 = j + K1;
#define R1(r) { x0 += x1; x1 = rotl32(x1, (r)); x1 ^= x0; }
    R1(13) R1(15) R1(26) R1(6)   x0 += K1; x1 += K2 + 1u;
    R1(17) R1(29) R1(16) R1(24)  x0 += K2; x1 += K0 + 2u;
    R1(13) R1(15) R1(26) R1(6)   x0 += K0; x1 += K1 + 3u;
    R1(17) R1(29) R1(16) R1(24)  x0 += K1; x1 += K2 + 4u;
    R1(13) R1(15) R1(26) R1(6)   x0 += K2; x1 += K0 + 5u;
#undef R1
    return x0 ^ x1;
}

__device__ __forceinline__ bool keepf(uint32_t j) {
    uint32_t bits = threefry_bits(j);
    float u = __uint_as_float((bits >> 9) | 0x3f800000u) - 1.0f;
    return u < 0.9f;
}

__global__ __launch_bounds__(NT, 2)
void attn_kernel(const float* __restrict__ Qg, const float* __restrict__ Kg,
                 const float* __restrict__ Vg, float* __restrict__ Og)
{
    extern __shared__ float sm[];
    float* Qs = sm + OFF_Q;
    float* Ks = sm + OFF_K;
    float* Sb = sm + OFF_S;
    unsigned* colhot = (unsigned*)(sm + OFF_C);

    const int tid = threadIdx.x;
    const int tx = tid & 15;
    const int ty = tid >> 4;
    const int b  = blockIdx.y;
    const int q0 = blockIdx.x * TQ;

    // ---- load Q tile [64][128], coalesced ----
    {
        const float* qp = Qg + ((size_t)(b * Qn + q0)) * Hn;
        #pragma unroll
        for (int e = 0; e < 8; e++) {
            int idx = tid + NT * e;
            int r = idx >> 5, c = (idx & 31) << 2;
            *(float4*)&Qs[r * LDQ + c] = *(const float4*)&qp[r * Hn + c];
        }
    }

    float m[4], z[4];
    #pragma unroll
    for (int i = 0; i < 4; i++) { m[i] = -INFINITY; z[i] = 0.0f; }
    float O[4][8];
    #pragma unroll
    for (int i = 0; i < 4; i++)
        #pragma unroll
        for (int c = 0; c < 8; c++) O[i][c] = 0.0f;

    for (int vt = 0; vt < Vv; vt += TV) {
        __syncthreads();  // prev PV done with Sb/colhot; K buffer free

        // ---- load K tile; zero colhot ----
        {
            const float* kp = Kg + ((size_t)(b * Vv + vt)) * Hn;
            #pragma unroll
            for (int e = 0; e < 8; e++) {
                int idx = tid + NT * e;
                int r = idx >> 5, c = (idx & 31) << 2;
                *(float4*)&Ks[r * LDQ + c] = *(const float4*)&kp[r * Hn + c];
            }
        }
        if (tid < 2) colhot[tid] = 0u;
        __syncthreads();

        // ---- S = Q K^T : 4x4 microtile (rows ty+16i, cols tx+16j) ----
        float acc[4][4];
        #pragma unroll
        for (int i = 0; i < 4; i++)
            #pragma unroll
            for (int j = 0; j < 4; j++) acc[i][j] = 0.0f;

        #pragma unroll 2
        for (int kk = 0; kk < Hn; kk += 4) {
            float4 qv[4], kv[4];
            #pragma unroll
            for (int i = 0; i < 4; i++)
                qv[i] = *(const float4*)&Qs[(ty + 16 * i) * LDQ + kk];
            #pragma unroll
            for (int j = 0; j < 4; j++)
                kv[j] = *(const float4*)&Ks[(tx + 16 * j) * LDQ + kk];
            #pragma unroll
            for (int i = 0; i < 4; i++)
                #pragma unroll
                for (int j = 0; j < 4; j++) {
                    acc[i][j] += qv[i].x * kv[j].x;
                    acc[i][j] += qv[i].y * kv[j].y;
                    acc[i][j] += qv[i].z * kv[j].z;
                    acc[i][j] += qv[i].w * kv[j].w;
                }
        }

        // ---- online softmax + sparse dropout; write masked P into Sb ----
        #pragma unroll
        for (int i = 0; i < 4; i++) {
            float s0 = acc[i][0] * SCALE_F, s1 = acc[i][1] * SCALE_F;
            float s2 = acc[i][2] * SCALE_F, s3 = acc[i][3] * SCALE_F;
            float t = fmaxf(fmaxf(s0, s1), fmaxf(s2, s3));
            #pragma unroll
            for (int o = 1; o < 16; o <<= 1)
                t = fmaxf(t, __shfl_xor_sync(0xffffffffu, t, o, 16));
            float nm = fmaxf(m[i], t);
            float al = __expf(m[i] - nm);
            float p0 = __expf(s0 - nm), p1 = __expf(s1 - nm);
            float p2 = __expf(s2 - nm), p3 = __expf(s3 - nm);
            float zs = p0 + p1 + p2 + p3;
            #pragma unroll
            for (int o = 1; o < 16; o <<= 1)
                zs += __shfl_xor_sync(0xffffffffu, zs, o, 16);
            z[i] = z[i] * al + zs;
            m[i] = nm;
            #pragma unroll
            for (int c = 0; c < 8; c++) O[i][c] *= al;

            float w0 = 0.0f, w1 = 0.0f, w2 = 0.0f, w3 = 0.0f;
            float pmax = fmaxf(fmaxf(p0, p1), fmaxf(p2, p3));
            // warp-uniform gate: body runs only if any lane has mass
            if (__any_sync(0xffffffffu, pmax > CUT)) {
                uint32_t base = (uint32_t)(b * Qn + q0 + ty + 16 * i) *
                                (uint32_t)Vv + (uint32_t)(vt + tx);
                if (p0 > CUT) {
                    atomicOr(&colhot[tx >> 5], 1u << (tx & 31));
                    if (keepf(base)) w0 = p0;
                }
                if (p1 > CUT) {
                    atomicOr(&colhot[(tx + 16) >> 5], 1u << ((tx + 16) & 31));
                    if (keepf(base + 16u)) w1 = p1;
                }
                if (p2 > CUT) {
                    atomicOr(&colhot[1], 1u << (tx & 31));
                    if (keepf(base + 32u)) w2 = p2;
                }
                if (p3 > CUT) {
                    atomicOr(&colhot[1], 1u << ((tx + 16) & 31));
                    if (keepf(base + 48u)) w3 = p3;
                }
            }
            float* srow = &Sb[(ty + 16 * i) * LDS + tx];
            srow[0]  = w0;
            srow[16] = w1;
            srow[32] = w2;
            srow[48] = w3;
        }
        __syncthreads();  // Sb + colhot visible

        // ---- sparse PV: only hot columns; V rows straight from L2 ----
        unsigned m0 = colhot[0], m1 = colhot[1];
        const float* vbase = Vg + ((size_t)(b * Vv + vt)) * Hn;
        #pragma unroll 1
        for (int w = 0; w < 2; w++) {
            unsigned msk = w ? m1 : m0;
            int voff = w ? 32 : 0;
            while (msk) {
                int v = voff + (__ffs(msk) - 1);
                msk &= msk - 1;
                float pp[4];
                #pragma unroll
                for (int i = 0; i < 4; i++)
                    pp[i] = Sb[(ty + 16 * i) * LDS + v];
                float4 va = *(const float4*)&vbase[(size_t)v * Hn + 4 * tx];
                float4 vb = *(const float4*)&vbase[(size_t)v * Hn + 64 + 4 * tx];
                #pragma unroll
                for (int i = 0; i < 4; i++) {
                    float p = pp[i];
                    O[i][0] += p * va.x; O[i][1] += p * va.y;
                    O[i][2] += p * va.z; O[i][3] += p * va.w;
                    O[i][4] += p * vb.x; O[i][5] += p * vb.y;
                    O[i][6] += p * vb.z; O[i][7] += p * vb.w;
                }
            }
        }
    }

    // ---- epilogue: out = O / (0.9 * Z) ----
    float* op = Og + ((size_t)(b * Qn + q0)) * Hn;
    #pragma unroll
    for (int i = 0; i < 4; i++) {
        int r = ty + 16 * i;
        float invz = 1.0f / (0.9f * z[i]);
        float4 o1 = make_float4(O[i][0] * invz, O[i][1] * invz,
                                O[i][2] * invz, O[i][3] * invz);
        float4 o2 = make_float4(O[i][4] * invz, O[i][5] * invz,
                                O[i][6] * invz, O[i][7] * invz);
        *(float4*)&op[r * Hn + 4 * tx] = o1;
        *(float4*)&op[r * Hn + 64 + 4 * tx] = o2;
    }
}

extern "C" void kernel_launch(void* const* d_in, const int* in_sizes, int n_in,
                              void* d_out, int out_size) {
    const float* Qg = (const float*)d_in[0];
    const float* Kg = (const float*)d_in[1];
    const float* Vg = (const float*)d_in[2];
    float* Og = (float*)d_out;
    (void)in_sizes; (void)n_in; (void)out_size;

    cudaFuncSetAttribute(attn_kernel,
                         cudaFuncAttributeMaxDynamicSharedMemorySize, SMEM_BYTES);
    dim3 grid(Qn / TQ, Bn);
    attn_kernel<<<grid, NT, SMEM_BYTES>>>(Qg, Kg, Vg, Og);
}

// round 8
// speedup vs baseline: 4.6536x; 2.7529x over previous
#include <cuda_runtime.h>
#include <cuda_bf16.h>
#include <cstdint>

// B=4, Q=V=4096, H=128; out = softmax(sqrt(128)*QK^T) with deterministic
// JAX dropout (p=0.1, key 42), then @V.
//
// 3-kernel plan:
//  A: fp32->bf16 convert of Q,K into static buffers; zero per-row counters.
//  B: bf16 mma.sync flash loop; per-row running max in registers; enqueue
//     candidate columns (approx logit within 26 of running max) to global
//     per-row buckets.
//  C: per row: exact fp32 logits for candidates, exact softmax over them,
//     threefry dropout, sparse PV, normalize by 1/(0.9*Z).

#define Bn 4
#define Qn 4096
#define Vv 4096
#define Hn 128
#define NROWS (Bn * Qn)          // 16384 global rows
#define CAP 192                  // candidate cap per row
#define MARGIN 26.0f

static constexpr float SCALE_F = 11.313708498984761f;  // sqrt(128)

// ---------------- static device scratch (no allocations) ----------------
__device__ __nv_bfloat16 g_Qb[Bn * Qn * Hn];
__device__ __nv_bfloat16 g_Kb[Bn * Vv * Hn];
__device__ unsigned g_cnt[NROWS];
__device__ unsigned g_col[NROWS * CAP];

// ---------------- threefry (validated rel_err 4.8e-8 in R3) -------------
__device__ __forceinline__ uint32_t rotl32(uint32_t x, int d) {
    return __funnelshift_l(x, x, d);
}
__device__ __forceinline__ uint32_t threefry_bits(uint32_t j) {
    const uint32_t K0 = 0u, K1 = 42u;
    const uint32_t K2 = 0x1BD11BDAu ^ K0 ^ K1;
    uint32_t x0 = K0, x1 = j + K1;
#define R1(r) { x0 += x1; x1 = rotl32(x1, (r)); x1 ^= x0; }
    R1(13) R1(15) R1(26) R1(6)   x0 += K1; x1 += K2 + 1u;
    R1(17) R1(29) R1(16) R1(24)  x0 += K2; x1 += K0 + 2u;
    R1(13) R1(15) R1(26) R1(6)   x0 += K0; x1 += K1 + 3u;
    R1(17) R1(29) R1(16) R1(24)  x0 += K1; x1 += K2 + 4u;
    R1(13) R1(15) R1(26) R1(6)   x0 += K2; x1 += K0 + 5u;
#undef R1
    return x0 ^ x1;
}
__device__ __forceinline__ bool keepf(uint32_t j) {
    uint32_t bits = threefry_bits(j);
    float u = __uint_as_float((bits >> 9) | 0x3f800000u) - 1.0f;
    return u < 0.9f;
}

// ---------------- kernel A: convert + zero counters ---------------------
__global__ void prep_kernel(const float* __restrict__ Qg,
                            const float* __restrict__ Kg)
{
    const int nvec = Bn * Qn * Hn / 4;  // 524288 float4 groups per array
    for (int i = blockIdx.x * blockDim.x + threadIdx.x; i < nvec;
         i += gridDim.x * blockDim.x) {
        float4 q = *(const float4*)&Qg[i * 4];
        float4 k = *(const float4*)&Kg[i * 4];
        ((__nv_bfloat162*)g_Qb)[i * 2]     = __floats2bfloat162_rn(q.x, q.y);
        ((__nv_bfloat162*)g_Qb)[i * 2 + 1] = __floats2bfloat162_rn(q.z, q.w);
        ((__nv_bfloat162*)g_Kb)[i * 2]     = __floats2bfloat162_rn(k.x, k.y);
        ((__nv_bfloat162*)g_Kb)[i * 2 + 1] = __floats2bfloat162_rn(k.z, k.w);
    }
    for (int i = blockIdx.x * blockDim.x + threadIdx.x; i < NROWS;
         i += gridDim.x * blockDim.x)
        g_cnt[i] = 0u;
}

// ---------------- kernel B: bf16 mma candidate search -------------------
// CTA tile: 128 Q-rows x 64 K-cols, 8 warps (16 rows each), k = 128.
#define LDQB 136   // bf16 row stride (272 B = 17*16B, conflict-free ldmatrix)
#define LDKB 136
#define QSM_BYTES (128 * LDQB * 2)   // 34816
#define KSM_OFF   QSM_BYTES
#define SMEM_B    (QSM_BYTES + 64 * LDKB * 2)  // + 17408 = 52224

__device__ __forceinline__ uint32_t s2u(const void* p) {
    return (uint32_t)__cvta_generic_to_shared(p);
}
__device__ __forceinline__ void ldmx4(uint32_t& r0, uint32_t& r1,
                                      uint32_t& r2, uint32_t& r3, uint32_t a) {
    asm volatile("ldmatrix.sync.aligned.m8n8.x4.shared.b16 {%0,%1,%2,%3},[%4];"
                 : "=r"(r0), "=r"(r1), "=r"(r2), "=r"(r3) : "r"(a));
}
__device__ __forceinline__ void mma16816(float* c, const uint32_t* a,
                                         uint32_t b0, uint32_t b1) {
    asm volatile(
        "mma.sync.aligned.m16n8k16.row.col.f32.bf16.bf16.f32 "
        "{%0,%1,%2,%3},{%4,%5,%6,%7},{%8,%9},{%0,%1,%2,%3};"
        : "+f"(c[0]), "+f"(c[1]), "+f"(c[2]), "+f"(c[3])
        : "r"(a[0]), "r"(a[1]), "r"(a[2]), "r"(a[3]), "r"(b0), "r"(b1));
}

__global__ __launch_bounds__(256, 2)
void qk_kernel()
{
    extern __shared__ char smem[];
    __nv_bfloat16* Qsm = (__nv_bfloat16*)smem;
    __nv_bfloat16* Ksm = (__nv_bfloat16*)(smem + KSM_OFF);

    const int tid  = threadIdx.x;
    const int wid  = tid >> 5;
    const int lane = tid & 31;
    const int b    = blockIdx.y;
    const int q0   = blockIdx.x * 128;
    const int m0   = wid * 16;

    // load Q tile [128][128] bf16 -> smem (16B chunks)
    {
        const uint4* src = (const uint4*)&g_Qb[((size_t)(b * Qn + q0)) * Hn];
        #pragma unroll
        for (int e = 0; e < 8; e++) {
            int ch = tid + 256 * e;            // 2048 chunks
            int r = ch >> 4, cc = ch & 15;
            *(uint4*)&Qsm[r * LDQB + cc * 8] = src[r * 16 + cc];
        }
    }
    __syncthreads();

    // preload A fragments: 8 k-steps x 4 regs
    uint32_t af[8][4];
    {
        int row = m0 + (lane & 7) + ((lane >> 3) & 1) * 8;
        int chi = (lane >> 4) * 8;
        #pragma unroll
        for (int ks = 0; ks < 8; ks++) {
            uint32_t a = s2u(&Qsm[row * LDQB + ks * 16 + chi]);
            ldmx4(af[ks][0], af[ks][1], af[ks][2], af[ks][3], a);
        }
    }

    float rmax0 = -1e30f, rmax1 = -1e30f;
    const int grp = lane >> 2;          // 0..7
    const int qd  = lane & 3;           // 0..3
    const unsigned gr0 = (unsigned)(b * Qn + q0 + m0 + grp);
    const unsigned gr1 = gr0 + 8u;

    for (int vt = 0; vt < 64; vt++) {
        __syncthreads();  // prev tile's ldmatrix done with Ksm
        {   // load K tile [64][128] bf16
            const uint4* src = (const uint4*)&g_Kb[((size_t)(b * Vv + vt * 64)) * Hn];
            #pragma unroll
            for (int e = 0; e < 4; e++) {
                int ch = tid + 256 * e;        // 1024 chunks
                int r = ch >> 4, cc = ch & 15;
                *(uint4*)&Ksm[r * LDKB + cc * 8] = src[r * 16 + cc];
            }
        }
        __syncthreads();

        float c[8][4];
        #pragma unroll
        for (int f = 0; f < 8; f++)
            #pragma unroll
            for (int j = 0; j < 4; j++) c[f][j] = 0.0f;

        // B addressing: tile = lane>>3: noct = fpair + (lane>>4),
        // koct = (lane>>3)&1, row-in-tile = lane&7
        const int brow = (lane & 7);
        const int bko  = ((lane >> 3) & 1) * 8;
        const int bno  = (lane >> 4);
        #pragma unroll
        for (int ks = 0; ks < 8; ks++) {
            #pragma unroll
            for (int fp = 0; fp < 8; fp += 2) {
                uint32_t b0, b1, b2, b3;
                uint32_t a = s2u(&Ksm[(8 * (fp + bno) + brow) * LDKB + ks * 16 + bko]);
                ldmx4(b0, b1, b2, b3, a);
                mma16816(c[fp],     af[ks], b0, b1);
                mma16816(c[fp + 1], af[ks], b2, b3);
            }
        }

        // epilogue: scale, running row max (registers), threshold, enqueue
        float tm0 = -1e30f, tm1 = -1e30f;
        #pragma unroll
        for (int f = 0; f < 8; f++) {
            c[f][0] *= SCALE_F; c[f][1] *= SCALE_F;
            c[f][2] *= SCALE_F; c[f][3] *= SCALE_F;
            tm0 = fmaxf(tm0, fmaxf(c[f][0], c[f][1]));
            tm1 = fmaxf(tm1, fmaxf(c[f][2], c[f][3]));
        }
        tm0 = fmaxf(tm0, __shfl_xor_sync(0xffffffffu, tm0, 1));
        tm0 = fmaxf(tm0, __shfl_xor_sync(0xffffffffu, tm0, 2));
        tm1 = fmaxf(tm1, __shfl_xor_sync(0xffffffffu, tm1, 1));
        tm1 = fmaxf(tm1, __shfl_xor_sync(0xffffffffu, tm1, 2));
        rmax0 = fmaxf(rmax0, tm0);
        rmax1 = fmaxf(rmax1, tm1);
        const float th0 = rmax0 - MARGIN, th1 = rmax1 - MARGIN;

        bool hot = false;
        #pragma unroll
        for (int f = 0; f < 8; f++)
            hot = hot | (c[f][0] > th0) | (c[f][1] > th0)
                      | (c[f][2] > th1) | (c[f][3] > th1);
        if (__any_sync(0xffffffffu, hot)) {
            #pragma unroll
            for (int f = 0; f < 8; f++) {
                unsigned colb = (unsigned)(vt * 64 + 8 * f + 2 * qd);
                if (c[f][0] > th0) {
                    unsigned p = atomicAdd(&g_cnt[gr0], 1u);
                    if (p < CAP) g_col[gr0 * CAP + p] = colb;
                }
                if (c[f][1] > th0) {
                    unsigned p = atomicAdd(&g_cnt[gr0], 1u);
                    if (p < CAP) g_col[gr0 * CAP + p] = colb + 1u;
                }
                if (c[f][2] > th1) {
                    unsigned p = atomicAdd(&g_cnt[gr1], 1u);
                    if (p < CAP) g_col[gr1 * CAP + p] = colb;
                }
                if (c[f][3] > th1) {
                    unsigned p = atomicAdd(&g_cnt[gr1], 1u);
                    if (p < CAP) g_col[gr1 * CAP + p] = colb + 1u;
                }
            }
        }
    }
}

// ---------------- kernel C: exact sparse softmax + dropout + PV ---------
__global__ __launch_bounds__(128, 8)
void pv_kernel(const float* __restrict__ Qg, const float* __restrict__ Kg,
               const float* __restrict__ Vg, float* __restrict__ Og)
{
    __shared__ unsigned scol[CAP];
    __shared__ float ss[CAP];    // exact logits, then exp values
    __shared__ float sw[CAP];    // masked exp values

    const int gid = blockIdx.x;          // 0..16383
    const int b   = gid >> 12;
    const int tid = threadIdx.x;
    const int wq  = tid >> 5;
    const int lane = tid & 31;

    unsigned count = g_cnt[gid];
    if (count > CAP) count = CAP;
    if (count == 0) { Og[(size_t)gid * Hn + tid] = 0.0f; return; }

    for (unsigned i = tid; i < count; i += 128)
        scol[i] = g_col[gid * CAP + i];
    __syncthreads();

    // exact logits: one warp per entry
    {
        float4 qv = *(const float4*)&Qg[(size_t)gid * Hn + lane * 4];
        for (unsigned i = wq; i < count; i += 4) {
            unsigned col = scol[i];
            float4 kv = *(const float4*)&Kg[((size_t)(b * Vv + col)) * Hn + lane * 4];
            float d = qv.x * kv.x + qv.y * kv.y + qv.z * kv.z + qv.w * kv.w;
            #pragma unroll
            for (int o = 16; o > 0; o >>= 1)
                d += __shfl_xor_sync(0xffffffffu, d, o);
            if (lane == 0) ss[i] = d * SCALE_F;
        }
    }
    __syncthreads();

    float M = -1e30f;
    for (unsigned i = 0; i < count; i++) M = fmaxf(M, ss[i]);

    for (unsigned i = tid; i < count; i += 128) {
        float e = __expf(ss[i] - M);
        uint32_t j = (unsigned)gid * 4096u + scol[i];
        sw[i] = keepf(j) ? e : 0.0f;
        ss[i] = e;   // unmasked exp, for Z
    }
    __syncthreads();

    float Z = 0.0f;
    for (unsigned i = 0; i < count; i++) Z += ss[i];

    float acc = 0.0f;
    for (unsigned i = 0; i < count; i++) {
        float w = sw[i];
        if (w != 0.0f)
            acc += w * Vg[((size_t)(b * Vv + scol[i])) * Hn + tid];
    }
    Og[(size_t)gid * Hn + tid] = acc / (0.9f * Z);
}

// ---------------- launcher ----------------------------------------------
extern "C" void kernel_launch(void* const* d_in, const int* in_sizes, int n_in,
                              void* d_out, int out_size) {
    const float* Qg = (const float*)d_in[0];
    const float* Kg = (const float*)d_in[1];
    const float* Vg = (const float*)d_in[2];
    float* Og = (float*)d_out;
    (void)in_sizes; (void)n_in; (void)out_size;

    cudaFuncSetAttribute(qk_kernel,
                         cudaFuncAttributeMaxDynamicSharedMemorySize, SMEM_B);

    prep_kernel<<<512, 256>>>(Qg, Kg);
    dim3 gb(Qn / 128, Bn);                 // 32 x 4 = 128 CTAs
    qk_kernel<<<gb, 256, SMEM_B>>>();
    pv_kernel<<<NROWS, 128>>>(Qg, Kg, Vg, Og);
}